// round 1
// baseline (speedup 1.0000x reference)
#include <cuda_runtime.h>

// C = triu(triu(A) @ triu(B)), N = 4096, fp32.
// C[r,c] = sum_{k=r}^{c} A[r,k]*B[k,c] for r<=c, else 0.

constexpr int NMAT = 4096;
constexpr int BM = 128;
constexpr int BN = 128;
constexpr int BK = 8;
constexpr int TM = 8;
constexpr int TN = 8;
constexpr int THREADS = (BM / TM) * (BN / TN);  // 256

__global__ __launch_bounds__(THREADS, 2)
void trimm_21053929685603(const float* __restrict__ A,
                          const float* __restrict__ B,
                          float* __restrict__ C)
{
    const int bc = blockIdx.x;   // column-block index
    const int br = blockIdx.y;   // row-block index
    const int row0 = br * BM;
    const int col0 = bc * BN;
    const int tid = threadIdx.x;

    // ------------------------------------------------------------------
    // Blocks strictly below the diagonal: output is exactly zero.
    // d_out is poisoned (0xAA) before timing, so we must write zeros.
    // ------------------------------------------------------------------
    if (br > bc) {
        const float4 z = make_float4(0.f, 0.f, 0.f, 0.f);
        float4* out = reinterpret_cast<float4*>(C + (size_t)row0 * NMAT + col0);
        const int row_f4 = NMAT / 4;   // float4 stride per matrix row
        // BM*BN/4 = 4096 float4 stores, 16 per thread
        #pragma unroll
        for (int i = 0; i < (BM * BN / 4) / THREADS; ++i) {
            int idx = tid + i * THREADS;
            int r = idx >> 5;        // idx / (BN/4)
            int c = idx & 31;        // idx % (BN/4)
            out[(size_t)r * row_f4 + c] = z;
        }
        return;
    }

    // ------------------------------------------------------------------
    // Compute block (br <= bc). k range: [row0, col0 + BN)
    // triu masks are applied at the shared-memory load:
    //   A[r,k] valid iff k >= r ; B[k,c] valid iff k <= c.
    // With both masks applied, rows r > c inside diagonal blocks get an
    // empty sum -> exact 0, so no output masking is needed.
    // ------------------------------------------------------------------
    __shared__ float As[BK][BM + 4];   // +4 pad: kill store bank conflicts
    __shared__ float Bs[BK][BN];

    const int ty = tid >> 4;       // 0..15  (row group)
    const int tx = tid & 15;       // 0..15  (col group)

    // A-tile load mapping: one float4 along k per thread
    const int a_row = tid >> 1;            // 0..127
    const int a_k   = (tid & 1) * 4;       // 0 or 4
    // B-tile load mapping: one float4 along columns per thread
    const int b_k   = tid >> 5;            // 0..7
    const int b_col = (tid & 31) * 4;      // 0..124

    float acc[TM][TN];
    #pragma unroll
    for (int i = 0; i < TM; ++i)
        #pragma unroll
        for (int j = 0; j < TN; ++j)
            acc[i][j] = 0.f;

    const int kt_begin = row0;          // k >= r >= row0
    const int kt_end   = col0 + BN;     // k <= c <= col0+BN-1  (exclusive bound)

    const int arow_g = row0 + a_row;
    const int cg     = col0 + b_col;

    for (int kt = kt_begin; kt < kt_end; kt += BK) {
        // ---- load A tile (masked: k >= r), transpose into As ----
        {
            const float4 av = *reinterpret_cast<const float4*>(
                A + (size_t)arow_g * NMAT + (kt + a_k));
            const int kg = kt + a_k;
            As[a_k + 0][a_row] = (kg + 0 >= arow_g) ? av.x : 0.f;
            As[a_k + 1][a_row] = (kg + 1 >= arow_g) ? av.y : 0.f;
            As[a_k + 2][a_row] = (kg + 2 >= arow_g) ? av.z : 0.f;
            As[a_k + 3][a_row] = (kg + 3 >= arow_g) ? av.w : 0.f;
        }
        // ---- load B tile (masked: k <= c) ----
        {
            const int bkg = kt + b_k;
            float4 bv = *reinterpret_cast<const float4*>(
                B + (size_t)bkg * NMAT + cg);
            bv.x = (bkg <= cg + 0) ? bv.x : 0.f;
            bv.y = (bkg <= cg + 1) ? bv.y : 0.f;
            bv.z = (bkg <= cg + 2) ? bv.z : 0.f;
            bv.w = (bkg <= cg + 3) ? bv.w : 0.f;
            *reinterpret_cast<float4*>(&Bs[b_k][b_col]) = bv;
        }
        __syncthreads();

        // ---- 8x8 register-tile FMA over BK ----
        #pragma unroll
        for (int kk = 0; kk < BK; ++kk) {
            float ar[TM], bb[TN];
            const float4 a0 = *reinterpret_cast<const float4*>(&As[kk][ty * TM + 0]);
            const float4 a1 = *reinterpret_cast<const float4*>(&As[kk][ty * TM + 4]);
            ar[0]=a0.x; ar[1]=a0.y; ar[2]=a0.z; ar[3]=a0.w;
            ar[4]=a1.x; ar[5]=a1.y; ar[6]=a1.z; ar[7]=a1.w;
            const float4 b0 = *reinterpret_cast<const float4*>(&Bs[kk][tx * TN + 0]);
            const float4 b1 = *reinterpret_cast<const float4*>(&Bs[kk][tx * TN + 4]);
            bb[0]=b0.x; bb[1]=b0.y; bb[2]=b0.z; bb[3]=b0.w;
            bb[4]=b1.x; bb[5]=b1.y; bb[6]=b1.z; bb[7]=b1.w;
            #pragma unroll
            for (int i = 0; i < TM; ++i)
                #pragma unroll
                for (int j = 0; j < TN; ++j)
                    acc[i][j] = fmaf(ar[i], bb[j], acc[i][j]);
        }
        __syncthreads();
    }

    // ---- epilogue: vectorized C store ----
    #pragma unroll
    for (int i = 0; i < TM; ++i) {
        float4* crow = reinterpret_cast<float4*>(
            C + (size_t)(row0 + ty * TM + i) * NMAT + col0 + tx * TN);
        crow[0] = make_float4(acc[i][0], acc[i][1], acc[i][2], acc[i][3]);
        crow[1] = make_float4(acc[i][4], acc[i][5], acc[i][6], acc[i][7]);
    }
}

extern "C" void kernel_launch(void* const* d_in, const int* in_sizes, int n_in,
                              void* d_out, int out_size) {
    const float* A = (const float*)d_in[0];
    const float* B = (const float*)d_in[1];
    float* C = (float*)d_out;
    dim3 grid(NMAT / BN, NMAT / BM);   // (32, 32): x = col blocks, y = row blocks
    trimm_21053929685603<<<grid, THREADS>>>(A, B, C);
}

// round 3
// speedup vs baseline: 5.0458x; 5.0458x over previous
#include <cuda_runtime.h>
#include <cuda_bf16.h>
#include <cstdint>

// C = triu(triu(A) @ triu(B)), N = 4096, fp32.
// Fast path (sm_103a cubin): split fp32 -> bf16 hi/lo (pre-masked triu), run 3
// tcgen05 bf16 MMAs per K16 step (h*h + h*l + l*h), fp32 accum in TMEM.
// Fallback path (arch-generic PTX pass, never expected to run on GB300):
// round-1 SIMT fp32 kernel reading A/B directly.

constexpr int NMAT = 4096;
constexpr int BT = 128;        // CTA tile M=N=128
constexpr int KC = 64;         // k-chunk (64 bf16 = 128B rows, SW128 native)
constexpr int THREADS = 256;

// Scratch: split/masked operands. A0/A1: [r][k] row-major. B0/B1: B^T, [c][k].
__device__ __align__(1024) __nv_bfloat16 gA0[(size_t)NMAT * NMAT];
__device__ __align__(1024) __nv_bfloat16 gA1[(size_t)NMAT * NMAT];
__device__ __align__(1024) __nv_bfloat16 gB0[(size_t)NMAT * NMAT];
__device__ __align__(1024) __nv_bfloat16 gB1[(size_t)NMAT * NMAT];

// ---------------------------------------------------------------- PTX helpers
__device__ __forceinline__ uint32_t smem_u32(const void* p) {
    uint32_t a;
    asm("{ .reg .u64 t; cvta.to.shared.u64 t, %1; cvt.u32.u64 %0, t; }"
        : "=r"(a) : "l"(p));
    return a;
}

#if defined(__CUDA_ARCH_FEAT_SM103_ALL) || !defined(__CUDA_ARCH__)
// tcgen05 helpers only exist in the arch-specific (sm_103a) device pass.
// (Host pass parses them too, which is harmless.)
__device__ __forceinline__ uint32_t elect_one() {
    uint32_t p;
    asm volatile("{ .reg .pred p; elect.sync _|p, 0xFFFFFFFF; selp.b32 %0,1,0,p; }"
                 : "=r"(p));
    return p;
}
__device__ __forceinline__ void mma_f16_ss(uint32_t d, uint64_t ad, uint64_t bd,
                                           uint32_t idesc, uint32_t en) {
    asm volatile(
        "{\n\t.reg .pred p;\n\tsetp.ne.u32 p, %5, 0;\n\t"
        "tcgen05.mma.cta_group::1.kind::f16 [%0], %1, %2, %3, {%4,%4,%4,%4}, p;\n\t}"
        :: "r"(d), "l"(ad), "l"(bd), "r"(idesc), "r"(0u), "r"(en) : "memory");
}
#define TC_ALLOC(sl, n)  asm volatile("tcgen05.alloc.cta_group::1.sync.aligned.shared::cta.b32 [%0], %1;" :: "r"(sl), "r"((uint32_t)(n)) : "memory")
#define TC_RELINQ()      asm volatile("tcgen05.relinquish_alloc_permit.cta_group::1.sync.aligned;")
#define TC_DEALLOC(t, n) asm volatile("tcgen05.dealloc.cta_group::1.sync.aligned.b32 %0, %1;" :: "r"(t), "r"((uint32_t)(n)))
#define TC_COMMIT(mb)    asm volatile("tcgen05.commit.cta_group::1.mbarrier::arrive::one.shared::cluster.b64 [%0];" :: "r"(mb) : "memory")
#define TC_FENCE_AFTER() asm volatile("tcgen05.fence::after_thread_sync;" ::: "memory")
#define TC_FENCE_BEFORE() asm volatile("tcgen05.fence::before_thread_sync;" ::: "memory")
#define TC_WAIT_LD()     asm volatile("tcgen05.wait::ld.sync.aligned;" ::: "memory")
#define FENCE_ASYNC()    asm volatile("fence.proxy.async.shared::cta;" ::: "memory")
#define MBAR_INIT(mb, c) asm volatile("mbarrier.init.shared.b64 [%0], %1;" :: "r"(mb), "r"((uint32_t)(c)) : "memory")

#define MBAR_WAIT_PARITY(mb, ph) do {                                           \
    uint32_t _m = (mb), _p = (ph), _d;                                          \
    asm volatile("{\n\t.reg .pred p;\n\t"                                       \
        "mbarrier.try_wait.parity.acquire.cta.shared::cta.b64 p, [%1], %2;\n\t" \
        "selp.b32 %0, 1, 0, p;\n\t}" : "=r"(_d) : "r"(_m), "r"(_p) : "memory"); \
    if (!_d) {                                                                  \
        asm volatile("{\n\t.reg .pred P1;\n\t"                                  \
        "WL_%=:\n\t"                                                            \
        "mbarrier.try_wait.parity.acquire.cta.shared::cta.b64 P1, [%0], %1, 0x989680;\n\t" \
        "@P1 bra.uni WD_%=;\n\t"                                                \
        "bra.uni WL_%=;\n\t"                                                    \
        "WD_%=:\n\t}" :: "r"(_m), "r"(_p) : "memory");                          \
    }                                                                           \
} while (0)

#define LDTM_X32(r, a)                                                          \
    asm volatile("tcgen05.ld.sync.aligned.32x32b.x32.b32 "                      \
        "{%0, %1, %2, %3, %4, %5, %6, %7, %8, %9, %10, %11, %12, %13, %14, %15,"\
        " %16, %17, %18, %19, %20, %21, %22, %23, %24, %25, %26, %27, %28, %29, %30, %31}, [%32];" \
        : "=r"((r)[0]), "=r"((r)[1]), "=r"((r)[2]), "=r"((r)[3]),               \
          "=r"((r)[4]), "=r"((r)[5]), "=r"((r)[6]), "=r"((r)[7]),               \
          "=r"((r)[8]), "=r"((r)[9]), "=r"((r)[10]), "=r"((r)[11]),             \
          "=r"((r)[12]), "=r"((r)[13]), "=r"((r)[14]), "=r"((r)[15]),           \
          "=r"((r)[16]), "=r"((r)[17]), "=r"((r)[18]), "=r"((r)[19]),           \
          "=r"((r)[20]), "=r"((r)[21]), "=r"((r)[22]), "=r"((r)[23]),           \
          "=r"((r)[24]), "=r"((r)[25]), "=r"((r)[26]), "=r"((r)[27]),           \
          "=r"((r)[28]), "=r"((r)[29]), "=r"((r)[30]), "=r"((r)[31])            \
        : "r"(a))
#endif  // tcgen05 helpers

// SW128 smem descriptor (K-major, 128B rows): layout=SW128, ver=1, SBO=64, LBO=1
constexpr uint64_t DESC_BASE_SW128 =
    (uint64_t(2) << 61) | (uint64_t(1) << 46) | (uint64_t(64) << 32) | (uint64_t(1) << 16);
__device__ __forceinline__ uint64_t mk_desc(uint32_t a) {
    return DESC_BASE_SW128 | ((uint64_t)(a >> 4) & 0x3FFF);
}

// ---------------------------------------------------------------- pre-passes
__global__ __launch_bounds__(256)
void split_a_kernel(const float* __restrict__ A) {
    int idx = blockIdx.x * 256 + threadIdx.x;   // over NMAT * NMAT/4
    int r  = idx >> 10;
    int k4 = (idx & 1023) << 2;
    float4 v = *reinterpret_cast<const float4*>(A + (size_t)r * NMAT + k4);
    float x[4];
    x[0] = (k4 + 0 >= r) ? v.x : 0.f;
    x[1] = (k4 + 1 >= r) ? v.y : 0.f;
    x[2] = (k4 + 2 >= r) ? v.z : 0.f;
    x[3] = (k4 + 3 >= r) ? v.w : 0.f;
    __nv_bfloat16 h[4], l[4];
    #pragma unroll
    for (int i = 0; i < 4; ++i) {
        h[i] = __float2bfloat16(x[i]);
        l[i] = __float2bfloat16(x[i] - __bfloat162float(h[i]));
    }
    __nv_bfloat162* d0 = reinterpret_cast<__nv_bfloat162*>(gA0 + (size_t)r * NMAT + k4);
    __nv_bfloat162* d1 = reinterpret_cast<__nv_bfloat162*>(gA1 + (size_t)r * NMAT + k4);
    __nv_bfloat162 p;
    p.x = h[0]; p.y = h[1]; d0[0] = p;
    p.x = h[2]; p.y = h[3]; d0[1] = p;
    p.x = l[0]; p.y = l[1]; d1[0] = p;
    p.x = l[2]; p.y = l[3]; d1[1] = p;
}

__global__ __launch_bounds__(256)
void split_bt_kernel(const float* __restrict__ B) {
    __shared__ float s[32][33];
    const int kb = blockIdx.y * 32, cb = blockIdx.x * 32;
    const int tx = threadIdx.x, ty = threadIdx.y;   // (32, 8)
    #pragma unroll
    for (int j = 0; j < 4; ++j) {
        int k = kb + ty + 8 * j, c = cb + tx;
        float v = B[(size_t)k * NMAT + c];
        s[ty + 8 * j][tx] = (k <= c) ? v : 0.f;
    }
    __syncthreads();
    #pragma unroll
    for (int j = 0; j < 4; ++j) {
        int c = cb + ty + 8 * j, k = kb + tx;
        float v = s[tx][ty + 8 * j];
        __nv_bfloat16 h = __float2bfloat16(v);
        __nv_bfloat16 l = __float2bfloat16(v - __bfloat162float(h));
        gB0[(size_t)c * NMAT + k] = h;
        gB1[(size_t)c * NMAT + k] = l;
    }
}

// ---------------------------------------------------------------- main GEMM
// smem layout (1024-aligned base): [0:4) tmem ptr, [8:16) mbar, tiles at +1024
constexpr int OFF_A0 = 1024;
constexpr int OFF_A1 = OFF_A0 + BT * 128;   // 128 rows x 128B
constexpr int OFF_B0 = OFF_A1 + BT * 128;
constexpr int OFF_B1 = OFF_B0 + BT * 128;
constexpr int SMEM_NEED = OFF_B1 + BT * 128 + 1024;   // + alignment slack

__device__ __forceinline__ void ldg_tile(const __nv_bfloat16* __restrict__ g,
                                         int grow0, int kt, uint4 r[4], int tid) {
    #pragma unroll
    for (int j = 0; j < 4; ++j) {
        int idx = tid + j * THREADS;
        int row = idx >> 3, c16 = idx & 7;
        r[j] = *reinterpret_cast<const uint4*>(
            g + (size_t)(grow0 + row) * NMAT + kt + c16 * 8);
    }
}
__device__ __forceinline__ void sts_tile(char* tile, const uint4 r[4], int tid) {
    #pragma unroll
    for (int j = 0; j < 4; ++j) {
        int idx = tid + j * THREADS;
        int row = idx >> 3, c16 = idx & 7;
        uint32_t off = row * 128 + c16 * 16;
        off ^= (off >> 3) & 0x70;           // SW128
        *reinterpret_cast<uint4*>(tile + off) = r[j];
    }
}

__global__ __launch_bounds__(THREADS, 1)
void trimm_tc_kernel(const float* __restrict__ A,
                     const float* __restrict__ B,
                     float* __restrict__ C) {
    const int bc = blockIdx.x, br = blockIdx.y;
    const int row0 = br * BT, col0 = bc * BT;
    const int tid = threadIdx.x;

    // Lower-triangular blocks: write zeros (out is poisoned). Common to both paths.
    if (br > bc) {
        const float4 z = make_float4(0.f, 0.f, 0.f, 0.f);
        float4* out = reinterpret_cast<float4*>(C + (size_t)row0 * NMAT + col0);
        #pragma unroll
        for (int i = 0; i < (BT * BT / 4) / THREADS; ++i) {
            int idx = tid + i * THREADS;
            out[(size_t)(idx >> 5) * (NMAT / 4) + (idx & 31)] = z;
        }
        return;
    }

#if defined(__CUDA_ARCH__) && !defined(__CUDA_ARCH_FEAT_SM103_ALL)
    // ---------------- arch-generic fallback: SIMT fp32 (round-1 kernel) ----
    constexpr int BK = 8, TM = 8, TN = 8;
    __shared__ float As[BK][BT + 4];
    __shared__ float Bs[BK][BT];

    const int ty = tid >> 4, tx = tid & 15;
    const int a_row = tid >> 1, a_k = (tid & 1) * 4;
    const int b_k = tid >> 5, b_col = (tid & 31) * 4;

    float acc[TM][TN];
    #pragma unroll
    for (int i = 0; i < TM; ++i)
        #pragma unroll
        for (int j = 0; j < TN; ++j) acc[i][j] = 0.f;

    const int arow_g = row0 + a_row, cg = col0 + b_col;
    for (int kt = row0; kt < col0 + BT; kt += BK) {
        {
            const float4 av = *reinterpret_cast<const float4*>(
                A + (size_t)arow_g * NMAT + (kt + a_k));
            const int kg = kt + a_k;
            As[a_k + 0][a_row] = (kg + 0 >= arow_g) ? av.x : 0.f;
            As[a_k + 1][a_row] = (kg + 1 >= arow_g) ? av.y : 0.f;
            As[a_k + 2][a_row] = (kg + 2 >= arow_g) ? av.z : 0.f;
            As[a_k + 3][a_row] = (kg + 3 >= arow_g) ? av.w : 0.f;
        }
        {
            const int bkg = kt + b_k;
            float4 bv = *reinterpret_cast<const float4*>(B + (size_t)bkg * NMAT + cg);
            bv.x = (bkg <= cg + 0) ? bv.x : 0.f;
            bv.y = (bkg <= cg + 1) ? bv.y : 0.f;
            bv.z = (bkg <= cg + 2) ? bv.z : 0.f;
            bv.w = (bkg <= cg + 3) ? bv.w : 0.f;
            *reinterpret_cast<float4*>(&Bs[b_k][b_col]) = bv;
        }
        __syncthreads();
        #pragma unroll
        for (int kk = 0; kk < BK; ++kk) {
            float ar[TM], bb[TN];
            const float4 a0 = *reinterpret_cast<const float4*>(&As[kk][ty * TM + 0]);
            const float4 a1 = *reinterpret_cast<const float4*>(&As[kk][ty * TM + 4]);
            ar[0]=a0.x; ar[1]=a0.y; ar[2]=a0.z; ar[3]=a0.w;
            ar[4]=a1.x; ar[5]=a1.y; ar[6]=a1.z; ar[7]=a1.w;
            const float4 b0 = *reinterpret_cast<const float4*>(&Bs[kk][tx * TN + 0]);
            const float4 b1 = *reinterpret_cast<const float4*>(&Bs[kk][tx * TN + 4]);
            bb[0]=b0.x; bb[1]=b0.y; bb[2]=b0.z; bb[3]=b0.w;
            bb[4]=b1.x; bb[5]=b1.y; bb[6]=b1.z; bb[7]=b1.w;
            #pragma unroll
            for (int i = 0; i < TM; ++i)
                #pragma unroll
                for (int j = 0; j < TN; ++j)
                    acc[i][j] = fmaf(ar[i], bb[j], acc[i][j]);
        }
        __syncthreads();
    }
    #pragma unroll
    for (int i = 0; i < TM; ++i) {
        float4* crow = reinterpret_cast<float4*>(
            C + (size_t)(row0 + ty * TM + i) * NMAT + col0 + tx * TN);
        crow[0] = make_float4(acc[i][0], acc[i][1], acc[i][2], acc[i][3]);
        crow[1] = make_float4(acc[i][4], acc[i][5], acc[i][6], acc[i][7]);
    }
#else
    // ---------------- sm_103a fast path: tcgen05 split-bf16 ----------------
    const int wid = tid >> 5, lid = tid & 31;

    extern __shared__ char dsm[];
    const uint32_t raw = smem_u32(dsm);
    const uint32_t sb = (raw + 1023u) & ~1023u;
    char* base = dsm + (sb - raw);
    const uint32_t s_tmemptr = sb;
    const uint32_t s_mbar = sb + 8;
    char* pA0 = base + OFF_A0;
    char* pA1 = base + OFF_A1;
    char* pB0 = base + OFF_B0;
    char* pB1 = base + OFF_B1;

    if (wid == 0) { TC_ALLOC(s_tmemptr, 128); TC_RELINQ(); }
    if (tid == 0) { MBAR_INIT(s_mbar, 1); }
    __syncthreads();
    uint32_t tmem;
    asm volatile("ld.shared.b32 %0, [%1];" : "=r"(tmem) : "r"(s_tmemptr));

    const bool lead = (wid == 0) ? (elect_one() != 0) : false;
    const int nch = (bc - br + 1) * 2;

    const uint64_t dA0 = mk_desc(sb + OFF_A0);
    const uint64_t dA1 = mk_desc(sb + OFF_A1);
    const uint64_t dB0 = mk_desc(sb + OFF_B0);
    const uint64_t dB1 = mk_desc(sb + OFF_B1);
    // idesc kind::f16: dtype=F32, a/btype=BF16, N=128, M=128
    const uint32_t idesc = (1u << 4) | (1u << 7) | (1u << 10) | (16u << 17) | (8u << 24);

    uint4 rA0[4], rA1[4], rB0[4], rB1[4];
    // prologue: chunk 0
    ldg_tile(gA0, row0, row0, rA0, tid);
    ldg_tile(gA1, row0, row0, rA1, tid);
    ldg_tile(gB0, col0, row0, rB0, tid);
    ldg_tile(gB1, col0, row0, rB1, tid);
    sts_tile(pA0, rA0, tid);
    sts_tile(pA1, rA1, tid);
    sts_tile(pB0, rB0, tid);
    sts_tile(pB1, rB1, tid);

    uint32_t accum = 0;
    for (int c = 0; c < nch; ++c) {
        __syncthreads();                       // STS of chunk c visible
        if (lead) {
            FENCE_ASYNC();
            #pragma unroll
            for (int s = 0; s < 4; ++s) {      // 4 K16 steps per 64-chunk
                mma_f16_ss(tmem, dA0 + 2 * s, dB0 + 2 * s, idesc, accum);
                accum = 1;
                mma_f16_ss(tmem, dA0 + 2 * s, dB1 + 2 * s, idesc, 1);
                mma_f16_ss(tmem, dA1 + 2 * s, dB0 + 2 * s, idesc, 1);
            }
            TC_COMMIT(s_mbar);
        }
        if (c + 1 < nch) {                     // prefetch next chunk into regs
            int kt = row0 + (c + 1) * KC;
            ldg_tile(gA0, row0, kt, rA0, tid);
            ldg_tile(gA1, row0, kt, rA1, tid);
            ldg_tile(gB0, col0, kt, rB0, tid);
            ldg_tile(gB1, col0, kt, rB1, tid);
        }
        MBAR_WAIT_PARITY(s_mbar, (uint32_t)(c & 1));   // MMA done reading smem
        if (c + 1 < nch) {
            sts_tile(pA0, rA0, tid);
            sts_tile(pA1, rA1, tid);
            sts_tile(pB0, rB0, tid);
            sts_tile(pB1, rB1, tid);
        }
    }

    // epilogue: D (128 rows x 128 fp32 cols) from TMEM
    TC_FENCE_AFTER();
    if (wid < 4) {
        #pragma unroll
        for (int b = 0; b < 128; b += 32) {
            uint32_t r[32];
            LDTM_X32(r, tmem + b);
            TC_WAIT_LD();
            float4* dst = reinterpret_cast<float4*>(
                C + (size_t)(row0 + wid * 32 + lid) * NMAT + col0 + b);
            #pragma unroll
            for (int q = 0; q < 8; ++q)
                dst[q] = make_float4(__uint_as_float(r[4 * q + 0]),
                                     __uint_as_float(r[4 * q + 1]),
                                     __uint_as_float(r[4 * q + 2]),
                                     __uint_as_float(r[4 * q + 3]));
        }
        TC_FENCE_BEFORE();
    }
    __syncthreads();
    if (wid == 0) { TC_DEALLOC(tmem, 128); }
#endif
}

// ---------------------------------------------------------------- launch
extern "C" void kernel_launch(void* const* d_in, const int* in_sizes, int n_in,
                              void* d_out, int out_size) {
    const float* A = (const float*)d_in[0];
    const float* B = (const float*)d_in[1];
    float* C = (float*)d_out;

    cudaFuncSetAttribute(trimm_tc_kernel,
                         cudaFuncAttributeMaxDynamicSharedMemorySize, SMEM_NEED);

    split_a_kernel<<<NMAT * (NMAT / 4) / 256, 256>>>(A);
    split_bt_kernel<<<dim3(NMAT / 32, NMAT / 32), dim3(32, 8)>>>(B);
    trimm_tc_kernel<<<dim3(NMAT / BT, NMAT / BT), THREADS, SMEM_NEED>>>(A, B, C);
}

// round 4
// speedup vs baseline: 5.4849x; 1.0870x over previous
#include <cuda_runtime.h>
#include <cuda_bf16.h>
#include <cstdint>

// C = triu(triu(A) @ triu(B)), N = 4096, fp32.
// Fast path (sm_103a): A split fp32->bf16 hi/lo fused in-kernel (triu-masked);
// B pre-split+transposed by one pre-pass kernel; 3 tcgen05 bf16 MMAs per K16
// (h*h + h*l + l*h), fp32 accum in TMEM. 128x256 tiles, double-buffered smem.
// Fallback (arch-generic PTX): SIMT fp32 kernel.

constexpr int NMAT = 4096;
constexpr int BM = 128;        // tile rows
constexpr int BN = 256;        // tile cols
constexpr int KC = 64;         // k-chunk (64 bf16 = 128B rows, SW128 native)
constexpr int THREADS = 256;

// Scratch: B^T split/masked. gB0/gB1: [c][k] bf16 row-major (K-major for MMA).
__device__ __align__(1024) __nv_bfloat16 gB0[(size_t)NMAT * NMAT];
__device__ __align__(1024) __nv_bfloat16 gB1[(size_t)NMAT * NMAT];

// ---------------------------------------------------------------- helpers
__device__ __forceinline__ uint32_t smem_u32(const void* p) {
    uint32_t a;
    asm("{ .reg .u64 t; cvta.to.shared.u64 t, %1; cvt.u32.u64 %0, t; }"
        : "=r"(a) : "l"(p));
    return a;
}

#if defined(__CUDA_ARCH_FEAT_SM103_ALL) || !defined(__CUDA_ARCH__)
__device__ __forceinline__ uint32_t elect_one() {
    uint32_t p;
    asm volatile("{ .reg .pred p; elect.sync _|p, 0xFFFFFFFF; selp.b32 %0,1,0,p; }"
                 : "=r"(p));
    return p;
}
__device__ __forceinline__ void mma_f16_ss(uint32_t d, uint64_t ad, uint64_t bd,
                                           uint32_t idesc, uint32_t en) {
    asm volatile(
        "{\n\t.reg .pred p;\n\tsetp.ne.u32 p, %5, 0;\n\t"
        "tcgen05.mma.cta_group::1.kind::f16 [%0], %1, %2, %3, {%4,%4,%4,%4}, p;\n\t}"
        :: "r"(d), "l"(ad), "l"(bd), "r"(idesc), "r"(0u), "r"(en) : "memory");
}
__device__ __forceinline__ void cp_async16(uint32_t dst, const void* src) {
    asm volatile("cp.async.cg.shared.global [%0], [%1], 16;"
                 :: "r"(dst), "l"(src) : "memory");
}
#define CP_COMMIT()      asm volatile("cp.async.commit_group;" ::: "memory")
#define CP_WAIT0()       asm volatile("cp.async.wait_group 0;" ::: "memory")
#define TC_ALLOC(sl, n)  asm volatile("tcgen05.alloc.cta_group::1.sync.aligned.shared::cta.b32 [%0], %1;" :: "r"(sl), "r"((uint32_t)(n)) : "memory")
#define TC_RELINQ()      asm volatile("tcgen05.relinquish_alloc_permit.cta_group::1.sync.aligned;")
#define TC_DEALLOC(t, n) asm volatile("tcgen05.dealloc.cta_group::1.sync.aligned.b32 %0, %1;" :: "r"(t), "r"((uint32_t)(n)))
#define TC_COMMIT(mb)    asm volatile("tcgen05.commit.cta_group::1.mbarrier::arrive::one.shared::cluster.b64 [%0];" :: "r"(mb) : "memory")
#define TC_FENCE_AFTER() asm volatile("tcgen05.fence::after_thread_sync;" ::: "memory")
#define TC_FENCE_BEFORE() asm volatile("tcgen05.fence::before_thread_sync;" ::: "memory")
#define TC_WAIT_LD()     asm volatile("tcgen05.wait::ld.sync.aligned;" ::: "memory")
#define FENCE_ASYNC()    asm volatile("fence.proxy.async.shared::cta;" ::: "memory")
#define MBAR_INIT(mb, c) asm volatile("mbarrier.init.shared.b64 [%0], %1;" :: "r"(mb), "r"((uint32_t)(c)) : "memory")

#define MBAR_WAIT_PARITY(mb, ph) do {                                           \
    uint32_t _m = (mb), _p = (ph), _d;                                          \
    asm volatile("{\n\t.reg .pred p;\n\t"                                       \
        "mbarrier.try_wait.parity.acquire.cta.shared::cta.b64 p, [%1], %2;\n\t" \
        "selp.b32 %0, 1, 0, p;\n\t}" : "=r"(_d) : "r"(_m), "r"(_p) : "memory"); \
    if (!_d) {                                                                  \
        asm volatile("{\n\t.reg .pred P1;\n\t"                                  \
        "WL_%=:\n\t"                                                            \
        "mbarrier.try_wait.parity.acquire.cta.shared::cta.b64 P1, [%0], %1, 0x989680;\n\t" \
        "@P1 bra.uni WD_%=;\n\t"                                                \
        "bra.uni WL_%=;\n\t"                                                    \
        "WD_%=:\n\t}" :: "r"(_m), "r"(_p) : "memory");                          \
    }                                                                           \
} while (0)

#define LDTM_X32(r, a)                                                          \
    asm volatile("tcgen05.ld.sync.aligned.32x32b.x32.b32 "                      \
        "{%0, %1, %2, %3, %4, %5, %6, %7, %8, %9, %10, %11, %12, %13, %14, %15,"\
        " %16, %17, %18, %19, %20, %21, %22, %23, %24, %25, %26, %27, %28, %29, %30, %31}, [%32];" \
        : "=r"((r)[0]), "=r"((r)[1]), "=r"((r)[2]), "=r"((r)[3]),               \
          "=r"((r)[4]), "=r"((r)[5]), "=r"((r)[6]), "=r"((r)[7]),               \
          "=r"((r)[8]), "=r"((r)[9]), "=r"((r)[10]), "=r"((r)[11]),             \
          "=r"((r)[12]), "=r"((r)[13]), "=r"((r)[14]), "=r"((r)[15]),           \
          "=r"((r)[16]), "=r"((r)[17]), "=r"((r)[18]), "=r"((r)[19]),           \
          "=r"((r)[20]), "=r"((r)[21]), "=r"((r)[22]), "=r"((r)[23]),           \
          "=r"((r)[24]), "=r"((r)[25]), "=r"((r)[26]), "=r"((r)[27]),           \
          "=r"((r)[28]), "=r"((r)[29]), "=r"((r)[30]), "=r"((r)[31])            \
        : "r"(a))
#endif  // tcgen05 helpers

// SW128 smem descriptor (K-major, 128B rows): layout=SW128, ver=1, SBO=64, LBO=1
constexpr uint64_t DESC_BASE_SW128 =
    (uint64_t(2) << 61) | (uint64_t(1) << 46) | (uint64_t(64) << 32) | (uint64_t(1) << 16);
__device__ __forceinline__ uint64_t mk_desc(uint32_t a) {
    return DESC_BASE_SW128 | ((uint64_t)(a >> 4) & 0x3FFF);
}

__device__ __forceinline__ uint32_t pack_bf16x2(float a, float b) {
    __nv_bfloat162 h = __halves2bfloat162(__float2bfloat16(a), __float2bfloat16(b));
    return *reinterpret_cast<uint32_t*>(&h);
}

// ---------------------------------------------------------------- B pre-pass
// gB0/gB1[c][k] = hi/lo bf16 of (k<=c ? B[k][c] : 0).  64x64 tiles, staged.
__global__ __launch_bounds__(256)
void split_bt_kernel(const float* __restrict__ B) {
    const int kb = blockIdx.y * 64, cb = blockIdx.x * 64;
    const int tid = threadIdx.x;

    if (kb > cb + 63) {   // fully masked region: zeros, no B read
        const uint4 z = make_uint4(0, 0, 0, 0);
        int u = tid * 2;
        int c = u >> 3, s = u & 7;
        uint4* p0 = reinterpret_cast<uint4*>(gB0 + (size_t)(cb + c) * NMAT + kb + s * 8);
        uint4* p1 = reinterpret_cast<uint4*>(gB1 + (size_t)(cb + c) * NMAT + kb + s * 8);
        p0[0] = z; p0[1] = z;
        p1[0] = z; p1[1] = z;
        return;
    }

    __shared__ float s[64][65];
    #pragma unroll
    for (int i = 0; i < 4; ++i) {
        int idx = tid + i * 256;
        int k = idx >> 4, cq = (idx & 15) * 4;
        float4 v = *reinterpret_cast<const float4*>(B + (size_t)(kb + k) * NMAT + cb + cq);
        int kg = kb + k;
        s[k][cq + 0] = (kg <= cb + cq + 0) ? v.x : 0.f;
        s[k][cq + 1] = (kg <= cb + cq + 1) ? v.y : 0.f;
        s[k][cq + 2] = (kg <= cb + cq + 2) ? v.z : 0.f;
        s[k][cq + 3] = (kg <= cb + cq + 3) ? v.w : 0.f;
    }
    __syncthreads();

    const int c = tid >> 2;
    const int ks = (tid & 3) * 16;
    float f[16];
    #pragma unroll
    for (int j = 0; j < 16; ++j) f[j] = s[ks + j][c];
    uint32_t h[8], l[8];
    #pragma unroll
    for (int j = 0; j < 8; ++j) {
        float x0 = f[2 * j], x1 = f[2 * j + 1];
        float h0 = __bfloat162float(__float2bfloat16(x0));
        float h1 = __bfloat162float(__float2bfloat16(x1));
        h[j] = pack_bf16x2(x0, x1);
        l[j] = pack_bf16x2(x0 - h0, x1 - h1);
    }
    uint4* p0 = reinterpret_cast<uint4*>(gB0 + (size_t)(cb + c) * NMAT + kb + ks);
    uint4* p1 = reinterpret_cast<uint4*>(gB1 + (size_t)(cb + c) * NMAT + kb + ks);
    p0[0] = make_uint4(h[0], h[1], h[2], h[3]);
    p0[1] = make_uint4(h[4], h[5], h[6], h[7]);
    p1[0] = make_uint4(l[0], l[1], l[2], l[3]);
    p1[1] = make_uint4(l[4], l[5], l[6], l[7]);
}

// ---------------------------------------------------------------- main GEMM
// smem: ctrl @ +0 (tmemptr @0, mbar0 @8, mbar1 @16); two 96KB buffers @ +1024.
constexpr int OFF_A0 = 0;
constexpr int OFF_A1 = 16384;
constexpr int OFF_B0 = 32768;
constexpr int OFF_B1 = 65536;
constexpr int BUF_SZ = 98304;
constexpr int SMEM_NEED = 1024 + 2 * BUF_SZ + 1024;

__global__ __launch_bounds__(THREADS, 1)
void trimm_tc_kernel(const float* __restrict__ A,
                     const float* __restrict__ B,
                     float* __restrict__ C) {
    const int bc2 = blockIdx.x, br = blockIdx.y;
    const int row0 = br * BM, col0 = bc2 * BN;
    const int tid = threadIdx.x;

    // Fully-lower tiles: write zeros (out is poisoned).
    if (row0 > col0 + BN - 1) {
        const float4 z = make_float4(0.f, 0.f, 0.f, 0.f);
        float4* out = reinterpret_cast<float4*>(C + (size_t)row0 * NMAT + col0);
        #pragma unroll
        for (int i = 0; i < (BM * BN / 4) / THREADS; ++i) {
            int idx = tid + i * THREADS;
            out[(size_t)(idx >> 6) * (NMAT / 4) + (idx & 63)] = z;
        }
        return;
    }

#if defined(__CUDA_ARCH__) && !defined(__CUDA_ARCH_FEAT_SM103_ALL)
    // ---------------- arch-generic fallback: SIMT fp32, two 128-col halves --
    constexpr int BK = 8, TM = 8, TN = 8;
    __shared__ float As[BK][128 + 4];
    __shared__ float Bs[BK][128];

    const int ty = tid >> 4, tx = tid & 15;
    const int a_row = tid >> 1, a_k = (tid & 1) * 4;
    const int b_k = tid >> 5, b_col = (tid & 31) * 4;
    const int arow_g = row0 + a_row;

    for (int h = 0; h < 2; ++h) {
        const int col0h = col0 + h * 128;
        if (row0 > col0h + 127) {   // left half fully below diagonal
            const float4 z = make_float4(0.f, 0.f, 0.f, 0.f);
            float4* out = reinterpret_cast<float4*>(C + (size_t)row0 * NMAT + col0h);
            #pragma unroll
            for (int i = 0; i < (BM * 128 / 4) / THREADS; ++i) {
                int idx = tid + i * THREADS;
                out[(size_t)(idx >> 5) * (NMAT / 4) + (idx & 31)] = z;
            }
            continue;
        }
        float acc[TM][TN];
        #pragma unroll
        for (int i = 0; i < TM; ++i)
            #pragma unroll
            for (int j = 0; j < TN; ++j) acc[i][j] = 0.f;
        const int cg = col0h + b_col;
        __syncthreads();
        for (int kt = row0; kt < col0h + 128; kt += BK) {
            {
                const float4 av = *reinterpret_cast<const float4*>(
                    A + (size_t)arow_g * NMAT + (kt + a_k));
                const int kg = kt + a_k;
                As[a_k + 0][a_row] = (kg + 0 >= arow_g) ? av.x : 0.f;
                As[a_k + 1][a_row] = (kg + 1 >= arow_g) ? av.y : 0.f;
                As[a_k + 2][a_row] = (kg + 2 >= arow_g) ? av.z : 0.f;
                As[a_k + 3][a_row] = (kg + 3 >= arow_g) ? av.w : 0.f;
            }
            {
                const int bkg = kt + b_k;
                float4 bv = *reinterpret_cast<const float4*>(B + (size_t)bkg * NMAT + cg);
                bv.x = (bkg <= cg + 0) ? bv.x : 0.f;
                bv.y = (bkg <= cg + 1) ? bv.y : 0.f;
                bv.z = (bkg <= cg + 2) ? bv.z : 0.f;
                bv.w = (bkg <= cg + 3) ? bv.w : 0.f;
                *reinterpret_cast<float4*>(&Bs[b_k][b_col]) = bv;
            }
            __syncthreads();
            #pragma unroll
            for (int kk = 0; kk < BK; ++kk) {
                float ar[TM], bb[TN];
                #pragma unroll
                for (int i = 0; i < TM; ++i) ar[i] = As[kk][ty * TM + i];
                #pragma unroll
                for (int j = 0; j < TN; ++j) bb[j] = Bs[kk][tx * TN + j];
                #pragma unroll
                for (int i = 0; i < TM; ++i)
                    #pragma unroll
                    for (int j = 0; j < TN; ++j)
                        acc[i][j] = fmaf(ar[i], bb[j], acc[i][j]);
            }
            __syncthreads();
        }
        #pragma unroll
        for (int i = 0; i < TM; ++i) {
            float4* crow = reinterpret_cast<float4*>(
                C + (size_t)(row0 + ty * TM + i) * NMAT + col0h + tx * TN);
            crow[0] = make_float4(acc[i][0], acc[i][1], acc[i][2], acc[i][3]);
            crow[1] = make_float4(acc[i][4], acc[i][5], acc[i][6], acc[i][7]);
        }
    }
#else
    // ---------------- sm_103a fast path: tcgen05, fused A-split, dbl-buffer --
    const int wid = tid >> 5, lid = tid & 31;

    extern __shared__ char dsm[];
    const uint32_t raw = smem_u32(dsm);
    const uint32_t sb = (raw + 1023u) & ~1023u;
    char* base = dsm + (sb - raw);
    const uint32_t s_tmemptr = sb;
    const uint32_t s_mbar0 = sb + 8;

    if (wid == 0) { TC_ALLOC(s_tmemptr, 256); TC_RELINQ(); }
    if (tid == 0) { MBAR_INIT(s_mbar0, 1); MBAR_INIT(s_mbar0 + 8, 1); }
    __syncthreads();
    uint32_t tmem;
    asm volatile("ld.shared.b32 %0, [%1];" : "=r"(tmem) : "r"(s_tmemptr));

    const bool lead = (wid == 0) ? (elect_one() != 0) : false;
    const int nch = (col0 + BN - row0) / KC;   // >= 2

    // idesc kind::f16: dtype=F32, a/btype=BF16, N=256, M=128
    const uint32_t idesc = (1u << 4) | (1u << 7) | (1u << 10)
                         | ((BN / 8) << 17) | ((BM / 16) << 24);

    for (int c = 0; c < nch; ++c) {
        const int b = c & 1;
        const uint32_t bb = sb + 1024 + b * BUF_SZ;
        char* buf = base + 1024 + b * BUF_SZ;
        const int kt = row0 + c * KC;

        if (c >= 2) MBAR_WAIT_PARITY(s_mbar0 + 8 * b, ((c >> 1) + 1) & 1);

        // ---- B: 256 rows x 64 k bf16, pre-split; cp.async 16B x16/thread ----
        #pragma unroll
        for (int j = 0; j < 8; ++j) {
            int idx = tid + j * THREADS;       // 0..2047
            int crow = idx >> 3;               // 0..255
            int seg = idx & 7;                 // 16B segment
            uint32_t off = crow * 128 + seg * 16;
            off ^= (off >> 3) & 0x70;          // SW128
            const __nv_bfloat16* s0 = gB0 + (size_t)(col0 + crow) * NMAT + kt + seg * 8;
            const __nv_bfloat16* s1 = gB1 + (size_t)(col0 + crow) * NMAT + kt + seg * 8;
            cp_async16(bb + OFF_B0 + off, s0);
            cp_async16(bb + OFF_B1 + off, s1);
        }
        CP_COMMIT();

        // ---- A: 128 x 64 fp32, fused triu-mask + hi/lo split ----
        #pragma unroll
        for (int j = 0; j < 8; ++j) {
            int idx = tid + j * THREADS;       // 0..2047
            int m = idx >> 4;                  // 0..127
            int q = idx & 15;                  // k-quad
            const int arow = row0 + m;
            const int kg = kt + q * 4;
            float4 v = *reinterpret_cast<const float4*>(
                A + (size_t)arow * NMAT + kg);
            float x0 = (kg + 0 >= arow) ? v.x : 0.f;
            float x1 = (kg + 1 >= arow) ? v.y : 0.f;
            float x2 = (kg + 2 >= arow) ? v.z : 0.f;
            float x3 = (kg + 3 >= arow) ? v.w : 0.f;
            float h0 = __bfloat162float(__float2bfloat16(x0));
            float h1 = __bfloat162float(__float2bfloat16(x1));
            float h2 = __bfloat162float(__float2bfloat16(x2));
            float h3 = __bfloat162float(__float2bfloat16(x3));
            uint32_t off = m * 128 + q * 8;
            off ^= (off >> 3) & 0x70;          // SW128 (8B chunk, bit3 free)
            *reinterpret_cast<uint2*>(buf + OFF_A0 + off) =
                make_uint2(pack_bf16x2(x0, x1), pack_bf16x2(x2, x3));
            *reinterpret_cast<uint2*>(buf + OFF_A1 + off) =
                make_uint2(pack_bf16x2(x0 - h0, x1 - h1), pack_bf16x2(x2 - h2, x3 - h3));
        }

        CP_WAIT0();
        __syncthreads();                       // all STS/cp.async visible

        if (lead) {
            FENCE_ASYNC();
            const uint64_t dA0 = mk_desc(bb + OFF_A0);
            const uint64_t dA1 = mk_desc(bb + OFF_A1);
            const uint64_t dB0 = mk_desc(bb + OFF_B0);
            const uint64_t dB1 = mk_desc(bb + OFF_B1);
            #pragma unroll
            for (int s = 0; s < 4; ++s) {      // 4 K16 steps per 64-chunk
                mma_f16_ss(tmem, dA0 + 2 * s, dB0 + 2 * s, idesc,
                           (c > 0 || s > 0) ? 1u : 0u);
                mma_f16_ss(tmem, dA0 + 2 * s, dB1 + 2 * s, idesc, 1u);
                mma_f16_ss(tmem, dA1 + 2 * s, dB0 + 2 * s, idesc, 1u);
            }
            TC_COMMIT(s_mbar0 + 8 * b);
        }
    }

    // final MMA done
    {
        const int L = nch - 1;
        MBAR_WAIT_PARITY(s_mbar0 + 8 * (L & 1), (L >> 1) & 1);
    }
    TC_FENCE_AFTER();

    // epilogue: 8 warps; warp w covers rows (w&3)*32+lid, cols half=(w>>2)*128
    {
        const int wsub = wid & 3, half = wid >> 2;
        const int r = row0 + wsub * 32 + lid;
        #pragma unroll
        for (int batch = 0; batch < 4; ++batch) {
            uint32_t rg[32];
            LDTM_X32(rg, tmem + half * 128 + batch * 32);
            TC_WAIT_LD();
            float4* dst = reinterpret_cast<float4*>(
                C + (size_t)r * NMAT + col0 + half * 128 + batch * 32);
            #pragma unroll
            for (int q = 0; q < 8; ++q)
                dst[q] = make_float4(__uint_as_float(rg[4 * q + 0]),
                                     __uint_as_float(rg[4 * q + 1]),
                                     __uint_as_float(rg[4 * q + 2]),
                                     __uint_as_float(rg[4 * q + 3]));
        }
        TC_FENCE_BEFORE();
    }
    __syncthreads();
    if (wid == 0) { TC_DEALLOC(tmem, 256); }
#endif
}

// ---------------------------------------------------------------- launch
extern "C" void kernel_launch(void* const* d_in, const int* in_sizes, int n_in,
                              void* d_out, int out_size) {
    const float* A = (const float*)d_in[0];
    const float* B = (const float*)d_in[1];
    float* C = (float*)d_out;

    cudaFuncSetAttribute(trimm_tc_kernel,
                         cudaFuncAttributeMaxDynamicSharedMemorySize, SMEM_NEED);

    split_bt_kernel<<<dim3(NMAT / 64, NMAT / 64), 256>>>(B);
    trimm_tc_kernel<<<dim3(NMAT / BN, NMAT / BM), THREADS, SMEM_NEED>>>(A, B, C);
}